// round 13
// baseline (speedup 1.0000x reference)
#include <cuda_runtime.h>
#include <cstdint>

// ---------------------------------------------------------------------------
// HydraAttention, TF32 tensor-core version (register-pipelined mainloop).
//   prep : RN-round x, Wqkv, Wout to tf32 precision
//   k1   : TF32 GEMM 16384x3072x1024 -> g_qkv (+bias, fp32 accum)
//   k2   : per-row inv L2 norms of q,k
//   k3   : deterministic 2-stage pool kv[b,d] = sum_t khat*v
//   k4   : A2 = rn_tf32(q * invq * kv)
//   k5   : TF32 GEMM 16384x1024x1024 -> out (+bias)
// GEMM: mma.sync.m16n8k8.tf32, CTA 128x256x32, warp 64x64, cp.async 3-stage,
//       double-buffered register fragments (LDS for ks+1 overlaps MMA of ks).
// ---------------------------------------------------------------------------

#define BATCH 4
#define SEQT  4096
#define DMODEL 1024
#define MROWS (BATCH * SEQT)          // 16384
#define N3D   (3 * DMODEL)            // 3072
#define TCHUNKS 32
#define TPER    (SEQT / TCHUNKS)      // 128

// GEMM tiling
#define BM 128
#define BN 256
#define BK 32
#define KITERS (DMODEL / BK)          // 32
#define AS_LD 36
#define BS_LD 264
#define AS_SZ (BM * AS_LD)
#define BS_SZ (BK * BS_LD)
#define STG_STRIDE (AS_SZ + BS_SZ)
#define SMEM_BYTES (3 * STG_STRIDE * 4)

// Scratch (device globals — allocation-free per harness rules)
__device__ float g_qkv[(size_t)MROWS * N3D];
__device__ float g_xr[(size_t)MROWS * DMODEL];
__device__ float g_a2[(size_t)MROWS * DMODEL];
__device__ float g_wqkvr[(size_t)DMODEL * N3D];
__device__ float g_woutr[(size_t)DMODEL * DMODEL];
__device__ float g_invq[MROWS];
__device__ float g_invk[MROWS];
__device__ float g_kvpart[TCHUNKS * BATCH * DMODEL];
__device__ float g_kv[BATCH * DMODEL];

// ---------------------------------------------------------------------------
__device__ __forceinline__ float rn_tf32(float f) {
    uint32_t u; asm("cvt.rna.tf32.f32 %0, %1;" : "=r"(u) : "f"(f));
    return __uint_as_float(u);
}
__device__ __forceinline__ void cp16(uint32_t s, const void* g) {
    asm volatile("cp.async.cg.shared.global [%0], [%1], 16;" :: "r"(s), "l"(g));
}
__device__ __forceinline__ void cp_commit() { asm volatile("cp.async.commit_group;"); }
__device__ __forceinline__ void cp_wait1()  { asm volatile("cp.async.wait_group 1;"); }

__device__ __forceinline__ void mma_tf32(float* c, const uint32_t* a, const uint32_t* b) {
    asm volatile(
        "mma.sync.aligned.m16n8k8.row.col.f32.tf32.tf32.f32 "
        "{%0,%1,%2,%3}, {%4,%5,%6,%7}, {%8,%9}, {%0,%1,%2,%3};"
        : "+f"(c[0]), "+f"(c[1]), "+f"(c[2]), "+f"(c[3])
        : "r"(a[0]), "r"(a[1]), "r"(a[2]), "r"(a[3]), "r"(b[0]), "r"(b[1]));
}

__device__ __forceinline__ void stage_issue(
    uint32_t smu, int stg, int tid,
    const float* __restrict__ A, int lda,
    const float* __restrict__ B, int ldb,
    int m0, int n0, int k0)
{
    uint32_t sa = smu + (uint32_t)(stg * STG_STRIDE) * 4u;
    uint32_t sb = sa + (uint32_t)AS_SZ * 4u;
    const float* Ab = A + (size_t)m0 * lda + k0;
    #pragma unroll
    for (int j = 0; j < 4; ++j) {
        int c = tid + j * 256;
        int r = c >> 3, col = (c & 7) << 2;
        cp16(sa + (uint32_t)(r * AS_LD + col) * 4u, Ab + (size_t)r * lda + col);
    }
    const float* Bb = B + (size_t)k0 * ldb + n0;
    #pragma unroll
    for (int j = 0; j < 8; ++j) {
        int c = tid + j * 256;
        int r = c >> 6, col = (c & 63) << 2;
        cp16(sb + (uint32_t)(r * BS_LD + col) * 4u, Bb + (size_t)r * ldb + col);
    }
}

// Load one ks-step's fragments (warp tile 64x64) into the given buffers.
__device__ __forceinline__ void load_frags(
    const float* __restrict__ As, const float* __restrict__ Bs, int ks,
    int wm, int wn, int gid, int tig,
    uint32_t af[4][4], uint32_t bf[8][2])
{
    #pragma unroll
    for (int i = 0; i < 4; ++i) {
        const float* ap = As + (wm * 64 + i * 16 + gid) * AS_LD + ks + tig;
        af[i][0] = __float_as_uint(ap[0]);
        af[i][1] = __float_as_uint(ap[8 * AS_LD]);
        af[i][2] = __float_as_uint(ap[4]);
        af[i][3] = __float_as_uint(ap[8 * AS_LD + 4]);
    }
    #pragma unroll
    for (int j = 0; j < 8; ++j) {
        const float* bp = Bs + (ks + tig) * BS_LD + wn * 64 + j * 8 + gid;
        bf[j][0] = __float_as_uint(bp[0]);
        bf[j][1] = __float_as_uint(bp[4 * BS_LD]);
    }
}

// ---------------------------------------------------------------------------
// TF32 GEMM: C[M,N] = A[M,K] @ B[K,N] + bias[N]
// ---------------------------------------------------------------------------
__global__ __launch_bounds__(256, 1)
void gemm_tf32_kernel(const float* __restrict__ A, int lda,
                      const float* __restrict__ B, int ldb,
                      const float* __restrict__ bias,
                      float* __restrict__ C, int ldc)
{
    extern __shared__ float sm[];
    uint32_t smu = (uint32_t)__cvta_generic_to_shared(sm);
    const int tid = threadIdx.x;
    const int m0  = blockIdx.y * BM;
    const int n0  = blockIdx.x * BN;
    const int w   = tid >> 5, l = tid & 31;
    const int wm  = w & 1;
    const int wn  = w >> 1;
    const int gid = l >> 2, tig = l & 3;

    float acc[4][8][4];
    #pragma unroll
    for (int i = 0; i < 4; ++i)
        #pragma unroll
        for (int j = 0; j < 8; ++j)
            #pragma unroll
            for (int q = 0; q < 4; ++q) acc[i][j][q] = 0.f;

    stage_issue(smu, 0, tid, A, lda, B, ldb, m0, n0, 0);  cp_commit();
    stage_issue(smu, 1, tid, A, lda, B, ldb, m0, n0, BK); cp_commit();
    cp_wait1();
    __syncthreads();

    // Double-buffered fragment registers
    uint32_t af[2][4][4], bf[2][8][2];
    load_frags(sm, sm + AS_SZ, 0, wm, wn, gid, tig, af[0], bf[0]);

    int s_cur = 0, s_fill = 2;
    for (int it = 0; it < KITERS; ++it) {
        if (it + 2 < KITERS)
            stage_issue(smu, s_fill, tid, A, lda, B, ldb, m0, n0, (it + 2) * BK);
        cp_commit();

        const float* As = sm + s_cur * STG_STRIDE;
        const float* Bs = As + AS_SZ;

        #pragma unroll
        for (int ks8 = 0; ks8 < 4; ++ks8) {
            const int cur = ks8 & 1;
            // Prefetch next ks fragments (overlaps the 32 MMAs below)
            if (ks8 < 3)
                load_frags(As, Bs, (ks8 + 1) * 8, wm, wn, gid, tig,
                           af[cur ^ 1], bf[cur ^ 1]);
            #pragma unroll
            for (int i = 0; i < 4; ++i)
                #pragma unroll
                for (int j = 0; j < 8; ++j)
                    mma_tf32(acc[i][j], af[cur][i], bf[cur][j]);
        }

        cp_wait1();
        __syncthreads();
        s_cur  = (s_cur  == 2) ? 0 : s_cur  + 1;
        s_fill = (s_fill == 2) ? 0 : s_fill + 1;
        if (it + 1 < KITERS) {
            const float* Asn = sm + s_cur * STG_STRIDE;
            // After 4 ks-steps parity returns to buffer 0
            load_frags(Asn, Asn + AS_SZ, 0, wm, wn, gid, tig, af[0], bf[0]);
        }
    }

    // Epilogue: bias + store
    #pragma unroll
    for (int i = 0; i < 4; ++i) {
        int r0 = m0 + wm * 64 + i * 16 + gid;
        #pragma unroll
        for (int j = 0; j < 8; ++j) {
            int col = n0 + wn * 64 + j * 8 + 2 * tig;
            float b0 = bias[col], b1 = bias[col + 1];
            float2 v0 = make_float2(acc[i][j][0] + b0, acc[i][j][1] + b1);
            float2 v1 = make_float2(acc[i][j][2] + b0, acc[i][j][3] + b1);
            *(float2*)&C[(size_t)r0 * ldc + col]       = v0;
            *(float2*)&C[(size_t)(r0 + 8) * ldc + col] = v1;
        }
    }
}

// ---------------------------------------------------------------------------
// Elementwise RN-round to tf32 precision
// ---------------------------------------------------------------------------
__global__ void round_tf32_kernel(const float* __restrict__ in,
                                  float* __restrict__ out, int n4)
{
    int i = blockIdx.x * 256 + threadIdx.x;
    if (i >= n4) return;
    float4 v = ((const float4*)in)[i];
    v.x = rn_tf32(v.x); v.y = rn_tf32(v.y);
    v.z = rn_tf32(v.z); v.w = rn_tf32(v.w);
    ((float4*)out)[i] = v;
}

// A2[m][k] = rn_tf32( q[m,k] * invq[m] * kv[batch(m), k] )
__global__ void scale_round_kernel()
{
    int i   = blockIdx.x * 256 + threadIdx.x;
    int row = i >> 8;
    int c   = (i & 255) << 2;
    float iq = g_invq[row];
    float4 q  = *(const float4*)(g_qkv + (size_t)row * N3D + c);
    float4 kv = *(const float4*)(g_kv + ((row >> 12) << 10) + c);
    float4 o;
    o.x = rn_tf32(q.x * iq * kv.x);
    o.y = rn_tf32(q.y * iq * kv.y);
    o.z = rn_tf32(q.z * iq * kv.z);
    o.w = rn_tf32(q.w * iq * kv.w);
    ((float4*)g_a2)[i] = o;
}

// ---------------------------------------------------------------------------
__global__ void rownorm_kernel()
{
    __shared__ float sqs[8], sks[8];
    const int r = blockIdx.x;
    const float* base = g_qkv + (size_t)r * N3D;

    float sq = 0.f, sk = 0.f;
    for (int d = threadIdx.x; d < DMODEL; d += 256) {
        float qv = base[d];
        float kv = base[DMODEL + d];
        sq += qv * qv;
        sk += kv * kv;
    }
    #pragma unroll
    for (int o = 16; o > 0; o >>= 1) {
        sq += __shfl_down_sync(0xffffffffu, sq, o);
        sk += __shfl_down_sync(0xffffffffu, sk, o);
    }
    const int w = threadIdx.x >> 5, l = threadIdx.x & 31;
    if (l == 0) { sqs[w] = sq; sks[w] = sk; }
    __syncthreads();
    if (threadIdx.x == 0) {
        float a = 0.f, b = 0.f;
        #pragma unroll
        for (int i = 0; i < 8; ++i) { a += sqs[i]; b += sks[i]; }
        g_invq[r] = rsqrtf(a);
        g_invk[r] = rsqrtf(b);
    }
}

__global__ void kvpool_partial_kernel()
{
    const int gi = blockIdx.x * 256 + threadIdx.x;
    const int b  = gi >> 10;
    const int d  = gi & (DMODEL - 1);
    const int t0 = blockIdx.y * TPER;

    const int row0 = b * SEQT + t0;
    const float* p = g_qkv + (size_t)row0 * N3D + d;

    float acc = 0.f;
    #pragma unroll 4
    for (int t = 0; t < TPER; ++t) {
        float ik = g_invk[row0 + t];
        acc += (p[DMODEL] * ik) * p[2 * DMODEL];
        p += N3D;
    }
    g_kvpart[blockIdx.y * (BATCH * DMODEL) + gi] = acc;
}

__global__ void kvpool_reduce_kernel()
{
    const int gi = blockIdx.x * 256 + threadIdx.x;
    float s = 0.f;
    #pragma unroll
    for (int c = 0; c < TCHUNKS; ++c)
        s += g_kvpart[c * (BATCH * DMODEL) + gi];
    g_kv[gi] = s;
}

// ---------------------------------------------------------------------------
extern "C" void kernel_launch(void* const* d_in, const int* in_sizes, int n_in,
                              void* d_out, int out_size)
{
    const float* x    = (const float*)d_in[0];
    const float* Wqkv = (const float*)d_in[1];
    const float* bqkv = (const float*)d_in[2];
    const float* Wout = (const float*)d_in[3];
    const float* bout = (const float*)d_in[4];
    float* out = (float*)d_out;

    float *qkv, *xr, *a2, *wqkvr, *woutr;
    cudaGetSymbolAddress((void**)&qkv,   g_qkv);
    cudaGetSymbolAddress((void**)&xr,    g_xr);
    cudaGetSymbolAddress((void**)&a2,    g_a2);
    cudaGetSymbolAddress((void**)&wqkvr, g_wqkvr);
    cudaGetSymbolAddress((void**)&woutr, g_woutr);

    cudaFuncSetAttribute(gemm_tf32_kernel,
                         cudaFuncAttributeMaxDynamicSharedMemorySize, SMEM_BYTES);

    round_tf32_kernel<<<(MROWS * DMODEL / 4) / 256, 256>>>(x, xr, MROWS * DMODEL / 4);
    round_tf32_kernel<<<(DMODEL * N3D / 4) / 256, 256>>>(Wqkv, wqkvr, DMODEL * N3D / 4);
    round_tf32_kernel<<<(DMODEL * DMODEL / 4) / 256, 256>>>(Wout, woutr, DMODEL * DMODEL / 4);

    gemm_tf32_kernel<<<dim3(N3D / BN, MROWS / BM), 256, SMEM_BYTES>>>(
        xr, DMODEL, wqkvr, N3D, bqkv, qkv, N3D);

    rownorm_kernel<<<MROWS, 256>>>();
    kvpool_partial_kernel<<<dim3(BATCH * DMODEL / 256, TCHUNKS), 256>>>();
    kvpool_reduce_kernel<<<BATCH * DMODEL / 256, 256>>>();

    scale_round_kernel<<<MROWS, 256>>>();

    gemm_tf32_kernel<<<dim3(DMODEL / BN, MROWS / BM), 256, SMEM_BYTES>>>(
        a2, DMODEL, woutr, DMODEL, bout, out, DMODEL);
}

// round 14
// speedup vs baseline: 1.0025x; 1.0025x over previous
#include <cuda_runtime.h>
#include <cstdint>

// ---------------------------------------------------------------------------
// HydraAttention, TF32 tensor-core version (register-pipelined mainloop).
//   prep : RN-round x, Wqkv, Wout to tf32 precision
//   k1   : TF32 GEMM 16384x3072x1024 -> g_qkv (+bias, fp32 accum)
//   k2   : per-row inv L2 norms of q,k
//   k3   : deterministic 2-stage pool kv[b,d] = sum_t khat*v
//   k4   : A2 = rn_tf32(q * invq * kv)
//   k5   : TF32 GEMM 16384x1024x1024 -> out (+bias)
// GEMM: mma.sync.m16n8k8.tf32, CTA 128x256x32, warp 64x64, cp.async 3-stage,
//       double-buffered register fragments (LDS for ks+1 overlaps MMA of ks).
// ---------------------------------------------------------------------------

#define BATCH 4
#define SEQT  4096
#define DMODEL 1024
#define MROWS (BATCH * SEQT)          // 16384
#define N3D   (3 * DMODEL)            // 3072
#define TCHUNKS 32
#define TPER    (SEQT / TCHUNKS)      // 128

// GEMM tiling
#define BM 128
#define BN 256
#define BK 32
#define KITERS (DMODEL / BK)          // 32
#define AS_LD 36
#define BS_LD 264
#define AS_SZ (BM * AS_LD)
#define BS_SZ (BK * BS_LD)
#define STG_STRIDE (AS_SZ + BS_SZ)
#define SMEM_BYTES (3 * STG_STRIDE * 4)

// Scratch (device globals — allocation-free per harness rules)
__device__ float g_qkv[(size_t)MROWS * N3D];
__device__ float g_xr[(size_t)MROWS * DMODEL];
__device__ float g_a2[(size_t)MROWS * DMODEL];
__device__ float g_wqkvr[(size_t)DMODEL * N3D];
__device__ float g_woutr[(size_t)DMODEL * DMODEL];
__device__ float g_invq[MROWS];
__device__ float g_invk[MROWS];
__device__ float g_kvpart[TCHUNKS * BATCH * DMODEL];
__device__ float g_kv[BATCH * DMODEL];

// ---------------------------------------------------------------------------
__device__ __forceinline__ float rn_tf32(float f) {
    uint32_t u; asm("cvt.rna.tf32.f32 %0, %1;" : "=r"(u) : "f"(f));
    return __uint_as_float(u);
}
__device__ __forceinline__ void cp16(uint32_t s, const void* g) {
    asm volatile("cp.async.cg.shared.global [%0], [%1], 16;" :: "r"(s), "l"(g));
}
__device__ __forceinline__ void cp_commit() { asm volatile("cp.async.commit_group;"); }
__device__ __forceinline__ void cp_wait1()  { asm volatile("cp.async.wait_group 1;"); }

__device__ __forceinline__ void mma_tf32(float* c, const uint32_t* a, const uint32_t* b) {
    asm volatile(
        "mma.sync.aligned.m16n8k8.row.col.f32.tf32.tf32.f32 "
        "{%0,%1,%2,%3}, {%4,%5,%6,%7}, {%8,%9}, {%0,%1,%2,%3};"
        : "+f"(c[0]), "+f"(c[1]), "+f"(c[2]), "+f"(c[3])
        : "r"(a[0]), "r"(a[1]), "r"(a[2]), "r"(a[3]), "r"(b[0]), "r"(b[1]));
}

__device__ __forceinline__ void stage_issue(
    uint32_t smu, int stg, int tid,
    const float* __restrict__ A, int lda,
    const float* __restrict__ B, int ldb,
    int m0, int n0, int k0)
{
    uint32_t sa = smu + (uint32_t)(stg * STG_STRIDE) * 4u;
    uint32_t sb = sa + (uint32_t)AS_SZ * 4u;
    const float* Ab = A + (size_t)m0 * lda + k0;
    #pragma unroll
    for (int j = 0; j < 4; ++j) {
        int c = tid + j * 256;
        int r = c >> 3, col = (c & 7) << 2;
        cp16(sa + (uint32_t)(r * AS_LD + col) * 4u, Ab + (size_t)r * lda + col);
    }
    const float* Bb = B + (size_t)k0 * ldb + n0;
    #pragma unroll
    for (int j = 0; j < 8; ++j) {
        int c = tid + j * 256;
        int r = c >> 6, col = (c & 63) << 2;
        cp16(sb + (uint32_t)(r * BS_LD + col) * 4u, Bb + (size_t)r * ldb + col);
    }
}

// Load one ks-step's fragments (warp tile 64x64) into the given buffers.
__device__ __forceinline__ void load_frags(
    const float* __restrict__ As, const float* __restrict__ Bs, int ks,
    int wm, int wn, int gid, int tig,
    uint32_t af[4][4], uint32_t bf[8][2])
{
    #pragma unroll
    for (int i = 0; i < 4; ++i) {
        const float* ap = As + (wm * 64 + i * 16 + gid) * AS_LD + ks + tig;
        af[i][0] = __float_as_uint(ap[0]);
        af[i][1] = __float_as_uint(ap[8 * AS_LD]);
        af[i][2] = __float_as_uint(ap[4]);
        af[i][3] = __float_as_uint(ap[8 * AS_LD + 4]);
    }
    #pragma unroll
    for (int j = 0; j < 8; ++j) {
        const float* bp = Bs + (ks + tig) * BS_LD + wn * 64 + j * 8 + gid;
        bf[j][0] = __float_as_uint(bp[0]);
        bf[j][1] = __float_as_uint(bp[4 * BS_LD]);
    }
}

// ---------------------------------------------------------------------------
// TF32 GEMM: C[M,N] = A[M,K] @ B[K,N] + bias[N]
// ---------------------------------------------------------------------------
__global__ __launch_bounds__(256, 1)
void gemm_tf32_kernel(const float* __restrict__ A, int lda,
                      const float* __restrict__ B, int ldb,
                      const float* __restrict__ bias,
                      float* __restrict__ C, int ldc)
{
    extern __shared__ float sm[];
    uint32_t smu = (uint32_t)__cvta_generic_to_shared(sm);
    const int tid = threadIdx.x;
    const int m0  = blockIdx.y * BM;
    const int n0  = blockIdx.x * BN;
    const int w   = tid >> 5, l = tid & 31;
    const int wm  = w & 1;
    const int wn  = w >> 1;
    const int gid = l >> 2, tig = l & 3;

    float acc[4][8][4];
    #pragma unroll
    for (int i = 0; i < 4; ++i)
        #pragma unroll
        for (int j = 0; j < 8; ++j)
            #pragma unroll
            for (int q = 0; q < 4; ++q) acc[i][j][q] = 0.f;

    stage_issue(smu, 0, tid, A, lda, B, ldb, m0, n0, 0);  cp_commit();
    stage_issue(smu, 1, tid, A, lda, B, ldb, m0, n0, BK); cp_commit();
    cp_wait1();
    __syncthreads();

    // Double-buffered fragment registers
    uint32_t af[2][4][4], bf[2][8][2];
    load_frags(sm, sm + AS_SZ, 0, wm, wn, gid, tig, af[0], bf[0]);

    int s_cur = 0, s_fill = 2;
    for (int it = 0; it < KITERS; ++it) {
        if (it + 2 < KITERS)
            stage_issue(smu, s_fill, tid, A, lda, B, ldb, m0, n0, (it + 2) * BK);
        cp_commit();

        const float* As = sm + s_cur * STG_STRIDE;
        const float* Bs = As + AS_SZ;

        #pragma unroll
        for (int ks8 = 0; ks8 < 4; ++ks8) {
            const int cur = ks8 & 1;
            // Prefetch next ks fragments (overlaps the 32 MMAs below)
            if (ks8 < 3)
                load_frags(As, Bs, (ks8 + 1) * 8, wm, wn, gid, tig,
                           af[cur ^ 1], bf[cur ^ 1]);
            #pragma unroll
            for (int i = 0; i < 4; ++i)
                #pragma unroll
                for (int j = 0; j < 8; ++j)
                    mma_tf32(acc[i][j], af[cur][i], bf[cur][j]);
        }

        cp_wait1();
        __syncthreads();
        s_cur  = (s_cur  == 2) ? 0 : s_cur  + 1;
        s_fill = (s_fill == 2) ? 0 : s_fill + 1;
        if (it + 1 < KITERS) {
            const float* Asn = sm + s_cur * STG_STRIDE;
            // After 4 ks-steps parity returns to buffer 0
            load_frags(Asn, Asn + AS_SZ, 0, wm, wn, gid, tig, af[0], bf[0]);
        }
    }

    // Epilogue: bias + store
    #pragma unroll
    for (int i = 0; i < 4; ++i) {
        int r0 = m0 + wm * 64 + i * 16 + gid;
        #pragma unroll
        for (int j = 0; j < 8; ++j) {
            int col = n0 + wn * 64 + j * 8 + 2 * tig;
            float b0 = bias[col], b1 = bias[col + 1];
            float2 v0 = make_float2(acc[i][j][0] + b0, acc[i][j][1] + b1);
            float2 v1 = make_float2(acc[i][j][2] + b0, acc[i][j][3] + b1);
            *(float2*)&C[(size_t)r0 * ldc + col]       = v0;
            *(float2*)&C[(size_t)(r0 + 8) * ldc + col] = v1;
        }
    }
}

// ---------------------------------------------------------------------------
// Elementwise RN-round to tf32 precision
// ---------------------------------------------------------------------------
__global__ void round_tf32_kernel(const float* __restrict__ in,
                                  float* __restrict__ out, int n4)
{
    int i = blockIdx.x * 256 + threadIdx.x;
    if (i >= n4) return;
    float4 v = ((const float4*)in)[i];
    v.x = rn_tf32(v.x); v.y = rn_tf32(v.y);
    v.z = rn_tf32(v.z); v.w = rn_tf32(v.w);
    ((float4*)out)[i] = v;
}

// A2[m][k] = rn_tf32( q[m,k] * invq[m] * kv[batch(m), k] )
__global__ void scale_round_kernel()
{
    int i   = blockIdx.x * 256 + threadIdx.x;
    int row = i >> 8;
    int c   = (i & 255) << 2;
    float iq = g_invq[row];
    float4 q  = *(const float4*)(g_qkv + (size_t)row * N3D + c);
    float4 kv = *(const float4*)(g_kv + ((row >> 12) << 10) + c);
    float4 o;
    o.x = rn_tf32(q.x * iq * kv.x);
    o.y = rn_tf32(q.y * iq * kv.y);
    o.z = rn_tf32(q.z * iq * kv.z);
    o.w = rn_tf32(q.w * iq * kv.w);
    ((float4*)g_a2)[i] = o;
}

// ---------------------------------------------------------------------------
__global__ void rownorm_kernel()
{
    __shared__ float sqs[8], sks[8];
    const int r = blockIdx.x;
    const float* base = g_qkv + (size_t)r * N3D;

    float sq = 0.f, sk = 0.f;
    for (int d = threadIdx.x; d < DMODEL; d += 256) {
        float qv = base[d];
        float kv = base[DMODEL + d];
        sq += qv * qv;
        sk += kv * kv;
    }
    #pragma unroll
    for (int o = 16; o > 0; o >>= 1) {
        sq += __shfl_down_sync(0xffffffffu, sq, o);
        sk += __shfl_down_sync(0xffffffffu, sk, o);
    }
    const int w = threadIdx.x >> 5, l = threadIdx.x & 31;
    if (l == 0) { sqs[w] = sq; sks[w] = sk; }
    __syncthreads();
    if (threadIdx.x == 0) {
        float a = 0.f, b = 0.f;
        #pragma unroll
        for (int i = 0; i < 8; ++i) { a += sqs[i]; b += sks[i]; }
        g_invq[r] = rsqrtf(a);
        g_invk[r] = rsqrtf(b);
    }
}

__global__ void kvpool_partial_kernel()
{
    const int gi = blockIdx.x * 256 + threadIdx.x;
    const int b  = gi >> 10;
    const int d  = gi & (DMODEL - 1);
    const int t0 = blockIdx.y * TPER;

    const int row0 = b * SEQT + t0;
    const float* p = g_qkv + (size_t)row0 * N3D + d;

    float acc = 0.f;
    #pragma unroll 4
    for (int t = 0; t < TPER; ++t) {
        float ik = g_invk[row0 + t];
        acc += (p[DMODEL] * ik) * p[2 * DMODEL];
        p += N3D;
    }
    g_kvpart[blockIdx.y * (BATCH * DMODEL) + gi] = acc;
}

__global__ void kvpool_reduce_kernel()
{
    const int gi = blockIdx.x * 256 + threadIdx.x;
    float s = 0.f;
    #pragma unroll
    for (int c = 0; c < TCHUNKS; ++c)
        s += g_kvpart[c * (BATCH * DMODEL) + gi];
    g_kv[gi] = s;
}

// ---------------------------------------------------------------------------
extern "C" void kernel_launch(void* const* d_in, const int* in_sizes, int n_in,
                              void* d_out, int out_size)
{
    const float* x    = (const float*)d_in[0];
    const float* Wqkv = (const float*)d_in[1];
    const float* bqkv = (const float*)d_in[2];
    const float* Wout = (const float*)d_in[3];
    const float* bout = (const float*)d_in[4];
    float* out = (float*)d_out;

    float *qkv, *xr, *a2, *wqkvr, *woutr;
    cudaGetSymbolAddress((void**)&qkv,   g_qkv);
    cudaGetSymbolAddress((void**)&xr,    g_xr);
    cudaGetSymbolAddress((void**)&a2,    g_a2);
    cudaGetSymbolAddress((void**)&wqkvr, g_wqkvr);
    cudaGetSymbolAddress((void**)&woutr, g_woutr);

    cudaFuncSetAttribute(gemm_tf32_kernel,
                         cudaFuncAttributeMaxDynamicSharedMemorySize, SMEM_BYTES);

    round_tf32_kernel<<<(MROWS * DMODEL / 4) / 256, 256>>>(x, xr, MROWS * DMODEL / 4);
    round_tf32_kernel<<<(DMODEL * N3D / 4) / 256, 256>>>(Wqkv, wqkvr, DMODEL * N3D / 4);
    round_tf32_kernel<<<(DMODEL * DMODEL / 4) / 256, 256>>>(Wout, woutr, DMODEL * DMODEL / 4);

    gemm_tf32_kernel<<<dim3(N3D / BN, MROWS / BM), 256, SMEM_BYTES>>>(
        xr, DMODEL, wqkvr, N3D, bqkv, qkv, N3D);

    rownorm_kernel<<<MROWS, 256>>>();
    kvpool_partial_kernel<<<dim3(BATCH * DMODEL / 256, TCHUNKS), 256>>>();
    kvpool_reduce_kernel<<<BATCH * DMODEL / 256, 256>>>();

    scale_round_kernel<<<MROWS, 256>>>();

    gemm_tf32_kernel<<<dim3(DMODEL / BN, MROWS / BM), 256, SMEM_BYTES>>>(
        a2, DMODEL, woutr, DMODEL, bout, out, DMODEL);
}